// round 3
// baseline (speedup 1.0000x reference)
#include <cuda_runtime.h>
#include <cuda_bf16.h>
#include <math.h>

// ---------------------------------------------------------------------------
// Problem constants
// ---------------------------------------------------------------------------
#define B 1024
#define NT 50
#define NC 200
#define EMB 128
#define NH 8
#define DK 32
#define DV 32
#define HD 256           // NH*DK = NH*DV
#define COS_EPS 1e-6f

#define MQ (B * NT)      // 51200
#define MK (B * NC)      // 204800

// Output element counts
#define OUT_ELEMS 6553600LL      // 1024*50*128
#define ATT_ELEMS 81920000LL     // 1024*8*50*200

// ---------------------------------------------------------------------------
// Scratch (static __device__ arrays; no allocation allowed)
// ---------------------------------------------------------------------------
__device__ float g_q  [(size_t)MQ * HD];   // projected queries  (b, t, 256)
__device__ float g_k  [(size_t)MK * HD];   // projected keys     (b, c, 256)
__device__ float g_v  [(size_t)MK * HD];   // projected values   (b, c, 256)
__device__ float g_qn [(size_t)B * NH * NT];
__device__ float g_kn [(size_t)B * NH * NC];
__device__ float g_ctx[(size_t)MQ * HD];   // attention context pre-R (b, t, 256)

// ---------------------------------------------------------------------------
// GEMM: C[M,N] = A[M,K] * W[N,K]^T + bias[N]
// BM=BN=128, BK=16, 256 threads, 8x8 register microtile.
// Requires M%128==0, N%128==0, K%16==0 (true for all uses here).
// ---------------------------------------------------------------------------
#define BM 128
#define BN 128
#define BKK 16
#define TM 8
#define TN 8

__global__ __launch_bounds__(256, 2)
void gemm_bias_kernel(const float* __restrict__ A, const float* __restrict__ W,
                      const float* __restrict__ bias, float* __restrict__ C,
                      int M, int N, int K) {
    __shared__ float As[BKK][BM];
    __shared__ float Ws[BKK][BN];

    const int tid = threadIdx.x;
    const int tr = tid >> 4;          // 0..15
    const int tc = tid & 15;          // 0..15
    const int row0 = blockIdx.y * BM;
    const int col0 = blockIdx.x * BN;

    float acc[TM][TN];
#pragma unroll
    for (int i = 0; i < TM; i++)
#pragma unroll
        for (int j = 0; j < TN; j++) acc[i][j] = 0.0f;

    const int lr = tid >> 2;          // 0..63
    const int lk = (tid & 3) << 2;    // 0,4,8,12

    for (int k0 = 0; k0 < K; k0 += BKK) {
#pragma unroll
        for (int s = 0; s < 2; s++) {
            int r = lr + s * 64;
            float4 av = *(const float4*)(A + (size_t)(row0 + r) * K + k0 + lk);
            As[lk + 0][r] = av.x; As[lk + 1][r] = av.y;
            As[lk + 2][r] = av.z; As[lk + 3][r] = av.w;
            float4 wv = *(const float4*)(W + (size_t)(col0 + r) * K + k0 + lk);
            Ws[lk + 0][r] = wv.x; Ws[lk + 1][r] = wv.y;
            Ws[lk + 2][r] = wv.z; Ws[lk + 3][r] = wv.w;
        }
        __syncthreads();

#pragma unroll
        for (int kk = 0; kk < BKK; kk++) {
            float af[TM], wf[TN];
#pragma unroll
            for (int i = 0; i < TM; i++) af[i] = As[kk][tr * TM + i];
#pragma unroll
            for (int j = 0; j < TN; j++) wf[j] = Ws[kk][tc * TN + j];
#pragma unroll
            for (int i = 0; i < TM; i++)
#pragma unroll
                for (int j = 0; j < TN; j++)
                    acc[i][j] = fmaf(af[i], wf[j], acc[i][j]);
        }
        __syncthreads();
    }

#pragma unroll
    for (int i = 0; i < TM; i++) {
        int r = row0 + tr * TM + i;
#pragma unroll
        for (int j = 0; j < TN; j += 4) {
            int ccol = col0 + tc * TN + j;
            float4 o;
            o.x = acc[i][j + 0] + bias[ccol + 0];
            o.y = acc[i][j + 1] + bias[ccol + 1];
            o.z = acc[i][j + 2] + bias[ccol + 2];
            o.w = acc[i][j + 3] + bias[ccol + 3];
            *(float4*)(C + (size_t)r * N + ccol) = o;
        }
    }
}

// ---------------------------------------------------------------------------
// Per-head L2 norms: Xn[(b*8+h)*n + c] = || X[(b*n+c)*256 + h*32 .. +31] ||
// ---------------------------------------------------------------------------
__global__ void norm_kernel(const float* __restrict__ X, float* __restrict__ Xn,
                            int n /* rows per batch */, int total /* B*n*8 */) {
    int i = blockIdx.x * blockDim.x + threadIdx.x;
    if (i >= total) return;
    int h = i & 7;
    int row = i >> 3;                 // b*n + c
    const float* p = X + (size_t)row * HD + h * DK;
    float s = 0.0f;
#pragma unroll
    for (int d = 0; d < DK; d += 4) {
        float4 v4 = *(const float4*)(p + d);
        s = fmaf(v4.x, v4.x, s); s = fmaf(v4.y, v4.y, s);
        s = fmaf(v4.z, v4.z, s); s = fmaf(v4.w, v4.w, s);
    }
    int b = row / n, c = row - b * n;
    Xn[((size_t)(b * NH + h)) * n + c] = sqrtf(s);
}

// ---------------------------------------------------------------------------
// Fused cosine attention per (b,h): scores -> softmax -> att out -> ctx
// 256 threads. smem layout (floats):
//   ks[32*201], vs[32*201], kn_s[200], pb_s[200], p_s[200], qs[32], red[32], part[256]
// ---------------------------------------------------------------------------
#define KS_STRIDE 201
#define ATTN_SMEM_FLOATS (2 * 32 * KS_STRIDE + 3 * 200 + 32 + 32 + 256 + 8)
#define ATTN_SMEM_BYTES (ATTN_SMEM_FLOATS * 4)

__global__ __launch_bounds__(256)
void attn_kernel(const float* __restrict__ q, const float* __restrict__ k,
                 const float* __restrict__ v, const float* __restrict__ qn,
                 const float* __restrict__ kn, const float* __restrict__ pos_bias,
                 float* __restrict__ att /* may be null */, float* __restrict__ ctx) {
    extern __shared__ float sm[];
    float* ks   = sm;
    float* vs   = ks + 32 * KS_STRIDE;
    float* kn_s = vs + 32 * KS_STRIDE;
    float* pb_s = kn_s + 200;
    float* p_s  = pb_s + 200;
    float* qs   = p_s + 200;
    float* red  = qs + 32;
    float* part = red + 32;
    __shared__ float qn_sh;

    const int bh = blockIdx.x;
    const int b  = bh >> 3;
    const int h  = bh & 7;
    const int tid = threadIdx.x;
    const int lane = tid & 31;
    const int wid = tid >> 5;

    // Stage this head's K,V slices (transposed: [d][c], stride 201 -> conflict-free)
    for (int i = tid; i < NC * 32; i += 256) {
        int c = i >> 5, d = i & 31;
        size_t gi = ((size_t)(b * NC + c)) * HD + h * DK + d;
        ks[d * KS_STRIDE + c] = k[gi];
        vs[d * KS_STRIDE + c] = v[gi];
    }
    if (tid < NC) {
        kn_s[tid] = kn[(size_t)bh * NC + tid];
        pb_s[tid] = pos_bias[tid];
    }
    __syncthreads();

    for (int t = 0; t < NT; t++) {
        if (tid < 32) qs[tid] = q[((size_t)(b * NT + t)) * HD + h * DK + tid];
        if (tid == 0) qn_sh = qn[(size_t)bh * NT + t];
        __syncthreads();

        float score = -1e30f;
        if (tid < NC) {
            float dot = 0.0f;
#pragma unroll
            for (int d = 0; d < 32; d++)
                dot = fmaf(qs[d], ks[d * KS_STRIDE + tid], dot);
            float den = fmaxf(qn_sh * kn_s[tid], COS_EPS);
            score = dot / den + pb_s[tid];
        }

        // block max
        float m = score;
#pragma unroll
        for (int o = 16; o; o >>= 1) m = fmaxf(m, __shfl_xor_sync(0xFFFFFFFFu, m, o));
        if (lane == 0) red[wid] = m;
        __syncthreads();
        m = red[0];
#pragma unroll
        for (int w = 1; w < 8; w++) m = fmaxf(m, red[w]);
        __syncthreads();   // all reads of red done before reuse

        float e = (tid < NC) ? __expf(score - m) : 0.0f;
        float s = e;
#pragma unroll
        for (int o = 16; o; o >>= 1) s += __shfl_xor_sync(0xFFFFFFFFu, s, o);
        if (lane == 0) red[wid] = s;
        __syncthreads();
        s = red[0];
#pragma unroll
        for (int w = 1; w < 8; w++) s += red[w];
        float inv_s = 1.0f / s;

        if (tid < NC) {
            float pv = e * inv_s;
            p_s[tid] = pv;
            if (att) att[((size_t)bh * NT + t) * NC + tid] = pv;
        }
        __syncthreads();

        // ctx[d] = sum_c p[c] * v[c][d]; 8 groups of 25 c each, per d
        {
            int d = tid & 31, g = tid >> 5;
            float partial = 0.0f;
            int cbeg = g * 25;
#pragma unroll
            for (int c = 0; c < 25; c++)
                partial = fmaf(p_s[cbeg + c], vs[d * KS_STRIDE + cbeg + c], partial);
            part[g * 32 + d] = partial;
        }
        __syncthreads();
        if (tid < 32) {
            float o = 0.0f;
#pragma unroll
            for (int g2 = 0; g2 < 8; g2++) o += part[g2 * 32 + tid];
            ctx[((size_t)(b * NT + t)) * HD + h * DK + tid] = o;
        }
        __syncthreads();  // protect qs/p_s/red before next t
    }
}

// ---------------------------------------------------------------------------
// Launch
// ---------------------------------------------------------------------------
extern "C" void kernel_launch(void* const* d_in, const int* in_sizes, int n_in,
                              void* d_out, int out_size) {
    const float* queries  = (const float*)d_in[0];
    const float* keys     = (const float*)d_in[1];
    const float* values   = (const float*)d_in[2];
    const float* At_w     = (const float*)d_in[3];
    const float* At_b     = (const float*)d_in[4];
    const float* Ac_w     = (const float*)d_in[5];
    const float* Ac_b     = (const float*)d_in[6];
    const float* Bc_w     = (const float*)d_in[7];
    const float* Bc_b     = (const float*)d_in[8];
    const float* pos_bias = (const float*)d_in[9];
    const float* R_w      = (const float*)d_in[10];
    const float* R_b      = (const float*)d_in[11];

    float *q, *k, *v, *qn, *kn, *ctx;
    cudaGetSymbolAddress((void**)&q,   g_q);
    cudaGetSymbolAddress((void**)&k,   g_k);
    cudaGetSymbolAddress((void**)&v,   g_v);
    cudaGetSymbolAddress((void**)&qn,  g_qn);
    cudaGetSymbolAddress((void**)&kn,  g_kn);
    cudaGetSymbolAddress((void**)&ctx, g_ctx);

    cudaFuncSetAttribute(attn_kernel, cudaFuncAttributeMaxDynamicSharedMemorySize,
                         ATTN_SMEM_BYTES);

    // Output layout: reference returns (out, att). Write out first, att after,
    // when out_size has room for both; degrade gracefully otherwise.
    float* out_ptr;
    float* att_ptr;
    long long osz = (long long)out_size;
    if (osz >= OUT_ELEMS + ATT_ELEMS) {
        out_ptr = (float*)d_out;
        att_ptr = (float*)d_out + OUT_ELEMS;
    } else if (osz == ATT_ELEMS) {
        att_ptr = (float*)d_out;
        out_ptr = q;              // scratch sink (unused output)
    } else {
        out_ptr = (float*)d_out;
        att_ptr = nullptr;
    }

    // Projections
    gemm_bias_kernel<<<dim3(HD / BN, MQ / BM), 256>>>(queries, At_w, At_b, q,  MQ, HD, EMB);
    gemm_bias_kernel<<<dim3(HD / BN, MK / BM), 256>>>(keys,    Ac_w, Ac_b, k,  MK, HD, EMB);
    gemm_bias_kernel<<<dim3(HD / BN, MK / BM), 256>>>(values,  Bc_w, Bc_b, v,  MK, HD, EMB);

    // Norms
    {
        int tq = B * NT * NH;
        int tk = B * NC * NH;
        norm_kernel<<<(tq + 255) / 256, 256>>>(q, qn, NT, tq);
        norm_kernel<<<(tk + 255) / 256, 256>>>(k, kn, NC, tk);
    }

    // Fused attention
    attn_kernel<<<B * NH, 256, ATTN_SMEM_BYTES>>>(q, k, v, qn, kn, pos_bias, att_ptr, ctx);

    // Output projection
    gemm_bias_kernel<<<dim3(EMB / BN, MQ / BM), 256>>>(ctx, R_w, R_b, out_ptr, MQ, EMB, HD);
}

// round 11
// speedup vs baseline: 1.7883x; 1.7883x over previous
#include <cuda_runtime.h>
#include <cuda_bf16.h>
#include <math.h>
#include <stdint.h>

// ---------------------------------------------------------------------------
// Problem constants
// ---------------------------------------------------------------------------
#define B 1024
#define NT 50
#define NC 200
#define EMB 128
#define NH 8
#define DK 32
#define DV 32
#define HD 256           // NH*DK = NH*DV
#define COS_EPS 1e-6f

#define MQ (B * NT)      // 51200
#define MK (B * NC)      // 204800

#define OUT_ELEMS 6553600LL      // 1024*50*128
#define ATT_ELEMS 81920000LL     // 1024*8*50*200

// ---------------------------------------------------------------------------
// Scratch
// ---------------------------------------------------------------------------
__device__ float g_q  [(size_t)MQ * HD];
__device__ float g_k  [(size_t)MK * HD];
__device__ float g_v  [(size_t)MK * HD];
__device__ float g_qn [(size_t)B * NH * NT];
__device__ float g_kn [(size_t)B * NH * NC];
__device__ float g_ctx[(size_t)MQ * HD];

// ---------------------------------------------------------------------------
// Split-bf16 tensor-core GEMM: C[M,N] = A[M,K] * W[N,K]^T + bias[N]
// ---------------------------------------------------------------------------
#define GBM 128
#define GBN 128
#define GBK 64
#define KPAD 72

#define GEMM_SMEM_BYTES (4 * 128 * KPAD * 2)

__device__ __forceinline__ uint32_t smem_u32(const void* p) {
    return (uint32_t)__cvta_generic_to_shared(p);
}

#define LDSM_X4(R, addr) \
    asm volatile("ldmatrix.sync.aligned.m8n8.x4.shared.b16 {%0,%1,%2,%3}, [%4];" \
        : "=r"((R)[0]), "=r"((R)[1]), "=r"((R)[2]), "=r"((R)[3]) : "r"(addr))

#define MMA16816(D, Ar, B0, B1) \
    asm volatile("mma.sync.aligned.m16n8k16.row.col.f32.bf16.bf16.f32 " \
        "{%0,%1,%2,%3}, {%4,%5,%6,%7}, {%8,%9}, {%0,%1,%2,%3};" \
        : "+f"((D)[0]), "+f"((D)[1]), "+f"((D)[2]), "+f"((D)[3]) \
        : "r"((Ar)[0]), "r"((Ar)[1]), "r"((Ar)[2]), "r"((Ar)[3]), "r"(B0), "r"(B1))

__global__ __launch_bounds__(256, 1)
void gemm_mma_kernel(const float* __restrict__ A, const float* __restrict__ W,
                     const float* __restrict__ bias, float* __restrict__ C,
                     int M, int N, int K) {
    extern __shared__ __nv_bfloat16 sm_bf[];
    __nv_bfloat16* a_hi = sm_bf;
    __nv_bfloat16* a_lo = a_hi + 128 * KPAD;
    __nv_bfloat16* w_hi = a_lo + 128 * KPAD;
    __nv_bfloat16* w_lo = w_hi + 128 * KPAD;

    const int tid  = threadIdx.x;
    const int lane = tid & 31;
    const int wid  = tid >> 5;
    const int wm   = wid & 3;
    const int wn   = wid >> 2;
    const int row0 = blockIdx.y * GBM;
    const int col0 = blockIdx.x * GBN;

    float acc[2][8][4];
#pragma unroll
    for (int i = 0; i < 2; i++)
#pragma unroll
        for (int j = 0; j < 8; j++)
#pragma unroll
            for (int r = 0; r < 4; r++) acc[i][j][r] = 0.0f;

    const int lr = tid >> 2;
    const int lc = (tid & 3) << 4;

    for (int k0 = 0; k0 < K; k0 += GBK) {
#pragma unroll
        for (int s = 0; s < 2; s++) {
            int rr = lr + s * 64;
            const float4* ap = (const float4*)(A + (size_t)(row0 + rr) * K + k0 + lc);
            const float4* wp = (const float4*)(W + (size_t)(col0 + rr) * K + k0 + lc);
            int base = rr * KPAD + lc;
#pragma unroll
            for (int j = 0; j < 4; j++) {
                float4 av = ap[j];
                __nv_bfloat162 h0 = __floats2bfloat162_rn(av.x, av.y);
                __nv_bfloat162 h1 = __floats2bfloat162_rn(av.z, av.w);
                __nv_bfloat162 l0 = __floats2bfloat162_rn(av.x - __bfloat162float(h0.x),
                                                          av.y - __bfloat162float(h0.y));
                __nv_bfloat162 l1 = __floats2bfloat162_rn(av.z - __bfloat162float(h1.x),
                                                          av.w - __bfloat162float(h1.y));
                *(__nv_bfloat162*)(a_hi + base + 4 * j)     = h0;
                *(__nv_bfloat162*)(a_hi + base + 4 * j + 2) = h1;
                *(__nv_bfloat162*)(a_lo + base + 4 * j)     = l0;
                *(__nv_bfloat162*)(a_lo + base + 4 * j + 2) = l1;

                float4 wv = wp[j];
                __nv_bfloat162 wh0 = __floats2bfloat162_rn(wv.x, wv.y);
                __nv_bfloat162 wh1 = __floats2bfloat162_rn(wv.z, wv.w);
                __nv_bfloat162 wl0 = __floats2bfloat162_rn(wv.x - __bfloat162float(wh0.x),
                                                           wv.y - __bfloat162float(wh0.y));
                __nv_bfloat162 wl1 = __floats2bfloat162_rn(wv.z - __bfloat162float(wh1.x),
                                                           wv.w - __bfloat162float(wh1.y));
                *(__nv_bfloat162*)(w_hi + base + 4 * j)     = wh0;
                *(__nv_bfloat162*)(w_hi + base + 4 * j + 2) = wh1;
                *(__nv_bfloat162*)(w_lo + base + 4 * j)     = wl0;
                *(__nv_bfloat162*)(w_lo + base + 4 * j + 2) = wl1;
            }
        }
        __syncthreads();

#pragma unroll
        for (int ks = 0; ks < GBK; ks += 16) {
            uint32_t ah[2][4], al[2][4];
#pragma unroll
            for (int mt = 0; mt < 2; mt++) {
                int mrow = wm * 32 + mt * 16 + (lane & 15);
                int mcol = ks + ((lane >> 4) << 3);
                LDSM_X4(ah[mt], smem_u32(a_hi + mrow * KPAD + mcol));
                LDSM_X4(al[mt], smem_u32(a_lo + mrow * KPAD + mcol));
            }
            uint32_t bh[4][4], bl[4][4];
#pragma unroll
            for (int nq = 0; nq < 4; nq++) {
                int nrow = wn * 64 + nq * 16 + (lane & 7) + ((lane >> 4) << 3);
                int ncol = ks + (((lane >> 3) & 1) << 3);
                LDSM_X4(bh[nq], smem_u32(w_hi + nrow * KPAD + ncol));
                LDSM_X4(bl[nq], smem_u32(w_lo + nrow * KPAD + ncol));
            }
#pragma unroll
            for (int mt = 0; mt < 2; mt++)
#pragma unroll
                for (int nt = 0; nt < 8; nt++) {
                    uint32_t* ph = &bh[nt >> 1][(nt & 1) * 2];
                    uint32_t* pl = &bl[nt >> 1][(nt & 1) * 2];
                    MMA16816(acc[mt][nt], ah[mt], ph[0], ph[1]);
                    MMA16816(acc[mt][nt], ah[mt], pl[0], pl[1]);
                    MMA16816(acc[mt][nt], al[mt], ph[0], ph[1]);
                }
        }
        __syncthreads();
    }

    const int g  = lane >> 2;
    const int tg = lane & 3;
#pragma unroll
    for (int mt = 0; mt < 2; mt++) {
        int r0 = row0 + wm * 32 + mt * 16 + g;
#pragma unroll
        for (int nt = 0; nt < 8; nt++) {
            int cc = col0 + wn * 64 + nt * 8 + tg * 2;
            float2 bz = *(const float2*)(bias + cc);
            float2 o0, o1;
            o0.x = acc[mt][nt][0] + bz.x;  o0.y = acc[mt][nt][1] + bz.y;
            o1.x = acc[mt][nt][2] + bz.x;  o1.y = acc[mt][nt][3] + bz.y;
            *(float2*)(C + (size_t)r0 * N + cc)       = o0;
            *(float2*)(C + (size_t)(r0 + 8) * N + cc) = o1;
        }
    }
}

// ---------------------------------------------------------------------------
// Per-head L2 norms
// ---------------------------------------------------------------------------
__global__ void norm_kernel(const float* __restrict__ X, float* __restrict__ Xn,
                            int n, int total) {
    int i = blockIdx.x * blockDim.x + threadIdx.x;
    if (i >= total) return;
    int h = i & 7;
    int row = i >> 3;
    const float* p = X + (size_t)row * HD + h * DK;
    float s = 0.0f;
#pragma unroll
    for (int d = 0; d < DK; d += 4) {
        float4 v4 = *(const float4*)(p + d);
        s = fmaf(v4.x, v4.x, s); s = fmaf(v4.y, v4.y, s);
        s = fmaf(v4.z, v4.z, s); s = fmaf(v4.w, v4.w, s);
    }
    int b = row / n, c = row - b * n;
    Xn[((size_t)(b * NH + h)) * n + c] = sqrtf(s);
}

// ---------------------------------------------------------------------------
// Fused cosine attention per (b,h): warp-per-query, barrier-free t-loop.
// smem (floats): ks[32][225], vs[32][225], qs[50][32], ps[8][200],
//                kn_s[224], pb_s[224], qn_s[64]
// K stride 225 (odd): conflict-free staging and reads.
// Columns 200..224 padded: ks=0, kn=0, pb=-1e30 -> softmax ignores them.
// ---------------------------------------------------------------------------
#define KSTR 225
#define ATTN_SMEM_FLOATS (2 * 32 * KSTR + NT * 32 + 8 * NC + 224 + 224 + 64)
#define ATTN_SMEM_BYTES (ATTN_SMEM_FLOATS * 4)

__global__ __launch_bounds__(256)
void attn_kernel(const float* __restrict__ q, const float* __restrict__ k,
                 const float* __restrict__ v, const float* __restrict__ qn,
                 const float* __restrict__ kn, const float* __restrict__ pos_bias,
                 float* __restrict__ att, float* __restrict__ ctx) {
    extern __shared__ float sm[];
    float* ks   = sm;                    // 7200
    float* vs   = ks + 32 * KSTR;        // 7200
    float* qs   = vs + 32 * KSTR;        // 1600
    float* ps   = qs + NT * 32;          // 1600
    float* kn_s = ps + 8 * NC;           // 224
    float* pb_s = kn_s + 224;            // 224
    float* qn_s = pb_s + 224;            // 64

    const int bh = blockIdx.x;
    const int b  = bh >> 3;
    const int h  = bh & 7;
    const int tid = threadIdx.x;
    const int lane = tid & 31;
    const int w = tid >> 5;

    // ---- stage K, V (transposed [d][c], stride 225) ----
    for (int i = tid; i < NC * 32; i += 256) {
        int c = i >> 5, d = i & 31;
        size_t gi = ((size_t)(b * NC + c)) * HD + h * DK + d;
        ks[d * KSTR + c] = k[gi];
        vs[d * KSTR + c] = v[gi];
    }
    // zero-pad ks columns [200,225)
    for (int i = tid; i < 32 * 25; i += 256) {
        int d = i / 25, c = NC + i % 25;
        ks[d * KSTR + c] = 0.0f;
    }
    // stage Q rows for all 50 queries
    for (int i = tid; i < NT * 32; i += 256) {
        int t = i >> 5, d = i & 31;
        qs[i] = q[((size_t)(b * NT + t)) * HD + h * DK + d];
    }
    if (tid < 224) {
        kn_s[tid] = (tid < NC) ? kn[(size_t)bh * NC + tid] : 0.0f;
        pb_s[tid] = (tid < NC) ? pos_bias[tid] : -1e30f;
    }
    if (tid < NT) qn_s[tid] = qn[(size_t)bh * NT + tid];
    __syncthreads();

    // per-lane cached kn / pb for the 7 owned columns
    float knr[7], pbr[7];
#pragma unroll
    for (int i = 0; i < 7; i++) {
        int c = lane + 32 * i;
        knr[i] = kn_s[c];
        pbr[i] = pb_s[c];
    }

    float* prow = ps + w * NC;
    const float* vrow = vs + lane * KSTR;

    const int nq = (w < 2) ? 7 : 6;      // queries per warp (50 = 2*7 + 6*6)
    for (int j = 0; j < nq; j++) {
        const int t = w + 8 * j;

        // ---- scores: lane owns c = lane + 32*i ----
        float acc[7];
#pragma unroll
        for (int i = 0; i < 7; i++) acc[i] = 0.0f;
        const float* qrow = qs + t * 32;
#pragma unroll
        for (int dc = 0; dc < 32; dc += 4) {
            float4 q4 = *(const float4*)(qrow + dc);   // warp-broadcast
#pragma unroll
            for (int i = 0; i < 7; i++) {
                int c = lane + 32 * i;
                acc[i] = fmaf(q4.x, ks[(dc + 0) * KSTR + c], acc[i]);
                acc[i] = fmaf(q4.y, ks[(dc + 1) * KSTR + c], acc[i]);
                acc[i] = fmaf(q4.z, ks[(dc + 2) * KSTR + c], acc[i]);
                acc[i] = fmaf(q4.w, ks[(dc + 3) * KSTR + c], acc[i]);
            }
        }

        // ---- cosine + bias, warp softmax ----
        const float qn_t = qn_s[t];
        float sc[7], m = -1e30f;
#pragma unroll
        for (int i = 0; i < 7; i++) {
            sc[i] = __fdividef(acc[i], fmaxf(qn_t * knr[i], COS_EPS)) + pbr[i];
            m = fmaxf(m, sc[i]);
        }
#pragma unroll
        for (int o = 16; o; o >>= 1) m = fmaxf(m, __shfl_xor_sync(0xFFFFFFFFu, m, o));
        float e[7], s = 0.0f;
#pragma unroll
        for (int i = 0; i < 7; i++) { e[i] = __expf(sc[i] - m); s += e[i]; }
#pragma unroll
        for (int o = 16; o; o >>= 1) s += __shfl_xor_sync(0xFFFFFFFFu, s, o);
        const float inv_s = 1.0f / s;

        // ---- write p to smem + att (coalesced) ----
        const size_t att_base = ((size_t)bh * NT + t) * NC;
#pragma unroll
        for (int i = 0; i < 7; i++) {
            int c = lane + 32 * i;
            float pv = e[i] * inv_s;
            if (c < NC) {
                prow[c] = pv;
                if (att) att[att_base + c] = pv;
            }
        }
        __syncwarp();

        // ---- PV: lane owns output dim d = lane ----
        float od = 0.0f;
#pragma unroll 5
        for (int c4 = 0; c4 < NC; c4 += 4) {
            float4 p4 = *(const float4*)(prow + c4);   // warp-broadcast
            od = fmaf(p4.x, vrow[c4 + 0], od);
            od = fmaf(p4.y, vrow[c4 + 1], od);
            od = fmaf(p4.z, vrow[c4 + 2], od);
            od = fmaf(p4.w, vrow[c4 + 3], od);
        }
        ctx[((size_t)(b * NT + t)) * HD + h * DK + lane] = od;
        __syncwarp();   // protect prow before next query overwrites
    }
}

// ---------------------------------------------------------------------------
// Launch
// ---------------------------------------------------------------------------
extern "C" void kernel_launch(void* const* d_in, const int* in_sizes, int n_in,
                              void* d_out, int out_size) {
    const float* queries  = (const float*)d_in[0];
    const float* keys     = (const float*)d_in[1];
    const float* values   = (const float*)d_in[2];
    const float* At_w     = (const float*)d_in[3];
    const float* At_b     = (const float*)d_in[4];
    const float* Ac_w     = (const float*)d_in[5];
    const float* Ac_b     = (const float*)d_in[6];
    const float* Bc_w     = (const float*)d_in[7];
    const float* Bc_b     = (const float*)d_in[8];
    const float* pos_bias = (const float*)d_in[9];
    const float* R_w      = (const float*)d_in[10];
    const float* R_b      = (const float*)d_in[11];

    float *q, *k, *v, *qn, *kn, *ctx;
    cudaGetSymbolAddress((void**)&q,   g_q);
    cudaGetSymbolAddress((void**)&k,   g_k);
    cudaGetSymbolAddress((void**)&v,   g_v);
    cudaGetSymbolAddress((void**)&qn,  g_qn);
    cudaGetSymbolAddress((void**)&kn,  g_kn);
    cudaGetSymbolAddress((void**)&ctx, g_ctx);

    cudaFuncSetAttribute(attn_kernel, cudaFuncAttributeMaxDynamicSharedMemorySize,
                         ATTN_SMEM_BYTES);
    cudaFuncSetAttribute(gemm_mma_kernel, cudaFuncAttributeMaxDynamicSharedMemorySize,
                         GEMM_SMEM_BYTES);

    float* out_ptr;
    float* att_ptr;
    long long osz = (long long)out_size;
    if (osz >= OUT_ELEMS + ATT_ELEMS) {
        out_ptr = (float*)d_out;
        att_ptr = (float*)d_out + OUT_ELEMS;
    } else if (osz == ATT_ELEMS) {
        att_ptr = (float*)d_out;
        out_ptr = q;
    } else {
        out_ptr = (float*)d_out;
        att_ptr = nullptr;
    }

    // Projections (split-bf16 tensor-core GEMMs)
    gemm_mma_kernel<<<dim3(HD / GBN, MQ / GBM), 256, GEMM_SMEM_BYTES>>>(queries, At_w, At_b, q,  MQ, HD, EMB);
    gemm_mma_kernel<<<dim3(HD / GBN, MK / GBM), 256, GEMM_SMEM_BYTES>>>(keys,    Ac_w, Ac_b, k,  MK, HD, EMB);
    gemm_mma_kernel<<<dim3(HD / GBN, MK / GBM), 256, GEMM_SMEM_BYTES>>>(values,  Bc_w, Bc_b, v,  MK, HD, EMB);

    // Norms
    {
        int tq = B * NT * NH;
        int tk = B * NC * NH;
        norm_kernel<<<(tq + 255) / 256, 256>>>(q, qn, NT, tq);
        norm_kernel<<<(tk + 255) / 256, 256>>>(k, kn, NC, tk);
    }

    // Fused attention (warp-per-query)
    attn_kernel<<<B * NH, 256, ATTN_SMEM_BYTES>>>(q, k, v, qn, kn, pos_bias, att_ptr, ctx);

    // Output projection
    gemm_mma_kernel<<<dim3(EMB / GBN, MQ / GBM), 256, GEMM_SMEM_BYTES>>>(ctx, R_w, R_b, out_ptr, MQ, EMB, HD);
}